// round 2
// baseline (speedup 1.0000x reference)
#include <cuda_runtime.h>
#include <cstdint>

typedef unsigned long long ull;

#define BB    8192
#define LL    128
#define OO    512
#define KK    8
#define HH    20

// per-o weight pair layout in shared (stride 641 pairs, odd -> conflict-free LDS.64):
// [0,180)   W1 (i*20+j)
// [180,200) b1
// [200,600) W2 (j*20+g)
// [600,620) b2
// [620,640) W3
// [640]     b3
#define OSTRIDE 641
#define OTILE   32
#define SMEM_PAIRS (OTILE * OSTRIDE)
#define SMEM_BYTES (SMEM_PAIRS * 8)

static __device__ __forceinline__ ull pack2(float lo, float hi) {
    ull r; asm("mov.b64 %0, {%1, %2};" : "=l"(r) : "f"(lo), "f"(hi)); return r;
}
static __device__ __forceinline__ float2 unpack2(ull v) {
    float2 f; asm("mov.b64 {%0, %1}, %2;" : "=f"(f.x), "=f"(f.y) : "l"(v)); return f;
}
static __device__ __forceinline__ ull dup2(float f) {
    ull r; asm("mov.b64 %0, {%1, %1};" : "=l"(r) : "f"(f)); return r;
}
static __device__ __forceinline__ ull fma2(ull a, ull b, ull c) {
    ull d; asm("fma.rn.f32x2 %0, %1, %2, %3;" : "=l"(d) : "l"(a), "l"(b), "l"(c)); return d;
}
static __device__ __forceinline__ ull mul2(ull a, ull b) {
    ull d; asm("mul.rn.f32x2 %0, %1, %2;" : "=l"(d) : "l"(a), "l"(b)); return d;
}
static __device__ __forceinline__ ull add2(ull a, ull b) {
    ull d; asm("add.rn.f32x2 %0, %1, %2;" : "=l"(d) : "l"(a), "l"(b)); return d;
}
static __device__ __forceinline__ float ex2_f(float x) {
    float r; asm("ex2.approx.f32 %0, %1;" : "=f"(r) : "f"(x)); return r;
}
static __device__ __forceinline__ float rcp_f(float x) {
    float r; asm("rcp.approx.f32 %0, %1;" : "=f"(r) : "f"(x)); return r;
}

// tanh(x) = 1 - 2/(exp(2x)+1), valid for all x (x->-inf: 1-2 = -1; x->+inf: 1-0 = 1)
static __device__ __forceinline__ ull tanh2(ull v) {
    const ull C2   = dup2(2.8853900817779268f);  // 2*log2(e)
    const ull ONE2 = dup2(1.0f);
    const ull M2   = dup2(-2.0f);
    ull m = mul2(v, C2);
    float2 mf = unpack2(m);
    float e0 = ex2_f(mf.x);
    float e1 = ex2_f(mf.y);
    ull s = add2(pack2(e0, e1), ONE2);
    float2 sf = unpack2(s);
    float r0 = rcp_f(sf.x);
    float r1 = rcp_f(sf.y);
    return fma2(pack2(r0, r1), M2, ONE2);   // 1 - 2*r
}

__global__ void __launch_bounds__(256, 1)
medil_kernel(const float* __restrict__ x,
             const float* __restrict__ noise,
             const int*   __restrict__ cause,
             const float* __restrict__ W1,
             const float* __restrict__ b1,
             const float* __restrict__ W2,
             const float* __restrict__ b2,
             const float* __restrict__ W3,
             const float* __restrict__ b3,
             float*       __restrict__ out)
{
    extern __shared__ ull wsm[];
    const int tid  = threadIdx.x;
    const int lane = tid & 31;
    const int warp = tid >> 5;
    const int oBase = blockIdx.x * OTILE;

    // Load weights for this block's 32 o's into shared, duplicated into f32x2 pairs.
    for (int idx = tid; idx < SMEM_PAIRS; idx += 256) {
        int ol  = idx / OSTRIDE;
        int off = idx - ol * OSTRIDE;
        int o   = oBase + ol;
        float v;
        if      (off < 180) v = W1[o * 180 + off];
        else if (off < 200) v = b1[o * 20 + (off - 180)];
        else if (off < 600) v = W2[o * 400 + (off - 200)];
        else if (off < 620) v = b2[o * 20 + (off - 600)];
        else if (off < 640) v = W3[o * 20 + (off - 620)];
        else                v = b3[o];
        wsm[idx] = pack2(v, v);
    }
    __syncthreads();

    const int o = oBase + lane;
    const ull* wb = wsm + lane * OSTRIDE;

    int c[KK];
#pragma unroll
    for (int k = 0; k < KK; k++) c[k] = cause[o * KK + k];

    const int blockB = blockIdx.y * 256;

#pragma unroll 1
    for (int it = 0; it < 8; ++it) {
        const int b0 = blockB + it * 32 + warp * 4;   // 4 consecutive b's per thread
        const float* xr = x + b0 * LL;

        // gather inputs: inp[pair][0]=noise, [k+1]=x[b, cause[o,k]]
        ull inp0[KK + 1], inp1[KK + 1];
        {
            float n0 = noise[(b0 + 0) * OO + o];
            float n1 = noise[(b0 + 1) * OO + o];
            float n2 = noise[(b0 + 2) * OO + o];
            float n3 = noise[(b0 + 3) * OO + o];
            inp0[0] = pack2(n0, n1);
            inp1[0] = pack2(n2, n3);
#pragma unroll
            for (int k = 0; k < KK; k++) {
                int cc = c[k];
                float a0 = xr[cc];
                float a1 = xr[LL + cc];
                float a2 = xr[2 * LL + cc];
                float a3 = xr[3 * LL + cc];
                inp0[k + 1] = pack2(a0, a1);
                inp1[k + 1] = pack2(a2, a3);
            }
        }

        // layer 1: h1[j] = tanh(b1[j] + sum_i inp[i] * W1[i][j])
        ull h10[HH], h11[HH];
#pragma unroll
        for (int j = 0; j < HH; j++) {
            ull a0 = wb[180 + j];
            ull a1 = a0;
#pragma unroll
            for (int i = 0; i < KK + 1; i++) {
                ull w = wb[i * 20 + j];
                a0 = fma2(inp0[i], w, a0);
                a1 = fma2(inp1[i], w, a1);
            }
            h10[j] = tanh2(a0);
            h11[j] = tanh2(a1);
        }

        // layers 2+3 fused: out += tanh(b2[g] + sum_j h1[j]*W2[j][g]) * W3[g]
        ull acc0 = wb[640];
        ull acc1 = acc0;
#pragma unroll
        for (int g = 0; g < HH; g++) {
            ull p0 = wb[600 + g];
            ull p1 = p0;
#pragma unroll
            for (int j = 0; j < HH; j++) {
                ull w = wb[200 + j * 20 + g];
                p0 = fma2(h10[j], w, p0);
                p1 = fma2(h11[j], w, p1);
            }
            ull w3p = wb[620 + g];
            acc0 = fma2(tanh2(p0), w3p, acc0);
            acc1 = fma2(tanh2(p1), w3p, acc1);
        }

        float2 r0 = unpack2(acc0);
        float2 r1 = unpack2(acc1);
        out[(b0 + 0) * OO + o] = r0.x;
        out[(b0 + 1) * OO + o] = r0.y;
        out[(b0 + 2) * OO + o] = r1.x;
        out[(b0 + 3) * OO + o] = r1.y;
    }
}

extern "C" void kernel_launch(void* const* d_in, const int* in_sizes, int n_in,
                              void* d_out, int out_size)
{
    const float* x     = (const float*)d_in[0];
    const float* noise = (const float*)d_in[1];
    const int*   cause = (const int*)  d_in[2];
    const float* W1    = (const float*)d_in[3];
    const float* b1    = (const float*)d_in[4];
    const float* W2    = (const float*)d_in[5];
    const float* b2    = (const float*)d_in[6];
    const float* W3    = (const float*)d_in[7];
    const float* b3    = (const float*)d_in[8];
    float* out = (float*)d_out;

    cudaFuncSetAttribute(medil_kernel,
                         cudaFuncAttributeMaxDynamicSharedMemorySize, SMEM_BYTES);

    dim3 grid(OO / OTILE, BB / 256);   // (16, 32) = 512 blocks
    medil_kernel<<<grid, 256, SMEM_BYTES>>>(x, noise, cause, W1, b1, W2, b2, W3, b3, out);
}

// round 3
// speedup vs baseline: 1.0094x; 1.0094x over previous
#include <cuda_runtime.h>
#include <cstdint>

typedef unsigned long long ull;

#define BB    8192
#define LL    128
#define OO    512
#define KK    8
#define HH    20

// Transposed per-o weight layout in shared (dup f32x2 pairs), OSTRIDE=642 pairs:
//  [0,200)   : 20 blocks of 10 pairs: [W1[0..8][j], b1[j]]      (j-th L1 neuron)
//  [200,640) : 20 blocks of 22 pairs: [W2[0..19][g], b2[g], W3[g]]
//  [640]     : b3
// OSTRIDE % 16 == 2 -> lane word-stride 4 banks -> LDS.128 conflict-free for 8 o's.
#define OSTRIDE 642
#define OTILE   8
#define SMEM_PAIRS (OTILE * OSTRIDE)
#define SMEM_BYTES (SMEM_PAIRS * 8)

static __device__ __forceinline__ ull pack2(float lo, float hi) {
    ull r; asm("mov.b64 %0, {%1, %2};" : "=l"(r) : "f"(lo), "f"(hi)); return r;
}
static __device__ __forceinline__ float2 unpack2(ull v) {
    float2 f; asm("mov.b64 {%0, %1}, %2;" : "=f"(f.x), "=f"(f.y) : "l"(v)); return f;
}
static __device__ __forceinline__ ull dup2(float f) {
    ull r; asm("mov.b64 %0, {%1, %1};" : "=l"(r) : "f"(f)); return r;
}
static __device__ __forceinline__ ull fma2(ull a, ull b, ull c) {
    ull d; asm("fma.rn.f32x2 %0, %1, %2, %3;" : "=l"(d) : "l"(a), "l"(b), "l"(c)); return d;
}
static __device__ __forceinline__ ull mul2(ull a, ull b) {
    ull d; asm("mul.rn.f32x2 %0, %1, %2;" : "=l"(d) : "l"(a), "l"(b)); return d;
}
static __device__ __forceinline__ ull add2(ull a, ull b) {
    ull d; asm("add.rn.f32x2 %0, %1, %2;" : "=l"(d) : "l"(a), "l"(b)); return d;
}
static __device__ __forceinline__ float ex2_f(float x) {
    float r; asm("ex2.approx.f32 %0, %1;" : "=f"(r) : "f"(x)); return r;
}
static __device__ __forceinline__ float rcp_f(float x) {
    float r; asm("rcp.approx.f32 %0, %1;" : "=f"(r) : "f"(x)); return r;
}

// tanh(x) = 1 - 2/(exp(2x)+1)  (exact limits at +/-inf; ~2ulp interior)
static __device__ __forceinline__ ull tanh2(ull v) {
    const ull C2   = dup2(2.8853900817779268f);  // 2*log2(e)
    const ull ONE2 = dup2(1.0f);
    const ull M2   = dup2(-2.0f);
    ull m = mul2(v, C2);
    float2 mf = unpack2(m);
    float e0 = ex2_f(mf.x);
    float e1 = ex2_f(mf.y);
    ull s = add2(pack2(e0, e1), ONE2);
    float2 sf = unpack2(s);
    float r0 = rcp_f(sf.x);
    float r1 = rcp_f(sf.y);
    return fma2(pack2(r0, r1), M2, ONE2);
}

__global__ void __launch_bounds__(128, 3)
medil_kernel(const float* __restrict__ x,
             const float* __restrict__ noise,
             const int*   __restrict__ cause,
             const float* __restrict__ W1,
             const float* __restrict__ b1,
             const float* __restrict__ W2,
             const float* __restrict__ b2,
             const float* __restrict__ W3,
             const float* __restrict__ b3,
             float*       __restrict__ out)
{
    extern __shared__ ull wsm[];
    const int tid   = threadIdx.x;
    const int oBase = blockIdx.x * OTILE;

    // ---- preamble: stage transposed dup-pair weights for 8 o's ----
#pragma unroll 1
    for (int ol = 0; ol < OTILE; ++ol) {
        const int o = oBase + ol;
        ull* dst = wsm + ol * OSTRIDE;
#pragma unroll 1
        for (int off = tid; off <= 640; off += 128) {
            float v;
            if (off < 200) {
                int j = off / 10;
                int r = off - j * 10;
                v = (r < 9) ? W1[o * 180 + r * 20 + j] : b1[o * 20 + j];
            } else if (off < 640) {
                int t = off - 200;
                int g = t / 22;
                int r = t - g * 22;
                if      (r < 20)  v = W2[o * 400 + r * 20 + g];
                else if (r == 20) v = b2[o * 20 + g];
                else              v = W3[o * 20 + g];
            } else {
                v = b3[o];
            }
            dst[off] = pack2(v, v);
        }
    }
    __syncthreads();

    const int o  = oBase + (tid & 7);
    const ull* wb = wsm + (tid & 7) * OSTRIDE;

    int c[KK];
    {
        int4 cA = *(const int4*)(cause + o * KK);
        int4 cB = *(const int4*)(cause + o * KK + 4);
        c[0] = cA.x; c[1] = cA.y; c[2] = cA.z; c[3] = cA.w;
        c[4] = cB.x; c[5] = cB.y; c[6] = cB.z; c[7] = cB.w;
    }

    const int bThread = blockIdx.y * 256 + (tid >> 3) * 2;  // this thread's first b

#pragma unroll 1
    for (int it = 0; it < 8; ++it) {
        const int b0 = bThread + it * 32;
        const float* xr = x + b0 * LL;

        // gather: inp[0] = noise pair, inp[k+1] = x[b, cause[o,k]] pair
        ull inp[KK + 1];
        inp[0] = pack2(noise[b0 * OO + o], noise[(b0 + 1) * OO + o]);
#pragma unroll
        for (int k = 0; k < KK; k++)
            inp[k + 1] = pack2(xr[c[k]], xr[LL + c[k]]);

        // ---- layer 1: h[j] = tanh(b1[j] + sum_i inp[i]*W1[i][j]) ----
        ull h[HH];
#pragma unroll
        for (int j = 0; j < HH; j++) {
            const ulonglong2* wj = (const ulonglong2*)(wb + j * 10);
            ulonglong2 q0 = wj[0];  // W1[0][j], W1[1][j]
            ulonglong2 q1 = wj[1];
            ulonglong2 q2 = wj[2];
            ulonglong2 q3 = wj[3];
            ulonglong2 q4 = wj[4];  // W1[8][j], b1[j]
            ull a = q4.y;
            a = fma2(inp[0], q0.x, a);
            a = fma2(inp[1], q0.y, a);
            a = fma2(inp[2], q1.x, a);
            a = fma2(inp[3], q1.y, a);
            a = fma2(inp[4], q2.x, a);
            a = fma2(inp[5], q2.y, a);
            a = fma2(inp[6], q3.x, a);
            a = fma2(inp[7], q3.y, a);
            a = fma2(inp[8], q4.x, a);
            h[j] = tanh2(a);
        }

        // ---- layers 2+3 fused: acc += tanh(b2[g] + sum_j h[j]*W2[j][g]) * W3[g] ----
        ull acc = wb[640];  // b3
#pragma unroll
        for (int g = 0; g < HH; g++) {
            const ulonglong2* wg = (const ulonglong2*)(wb + 200 + g * 22);
            ulonglong2 r0 = wg[0];
            ulonglong2 r1 = wg[1];
            ulonglong2 r2 = wg[2];
            ulonglong2 r3 = wg[3];
            ulonglong2 r4 = wg[4];
            ulonglong2 r5 = wg[5];
            ulonglong2 r6 = wg[6];
            ulonglong2 r7 = wg[7];
            ulonglong2 r8 = wg[8];
            ulonglong2 r9 = wg[9];
            ulonglong2 rA = wg[10];  // b2[g], W3[g]
            ull p = rA.x;
            p = fma2(h[0],  r0.x, p);
            p = fma2(h[1],  r0.y, p);
            p = fma2(h[2],  r1.x, p);
            p = fma2(h[3],  r1.y, p);
            p = fma2(h[4],  r2.x, p);
            p = fma2(h[5],  r2.y, p);
            p = fma2(h[6],  r3.x, p);
            p = fma2(h[7],  r3.y, p);
            p = fma2(h[8],  r4.x, p);
            p = fma2(h[9],  r4.y, p);
            p = fma2(h[10], r5.x, p);
            p = fma2(h[11], r5.y, p);
            p = fma2(h[12], r6.x, p);
            p = fma2(h[13], r6.y, p);
            p = fma2(h[14], r7.x, p);
            p = fma2(h[15], r7.y, p);
            p = fma2(h[16], r8.x, p);
            p = fma2(h[17], r8.y, p);
            p = fma2(h[18], r9.x, p);
            p = fma2(h[19], r9.y, p);
            acc = fma2(tanh2(p), rA.y, acc);
        }

        float2 r = unpack2(acc);
        out[b0 * OO + o]       = r.x;
        out[(b0 + 1) * OO + o] = r.y;
    }
}

extern "C" void kernel_launch(void* const* d_in, const int* in_sizes, int n_in,
                              void* d_out, int out_size)
{
    const float* x     = (const float*)d_in[0];
    const float* noise = (const float*)d_in[1];
    const int*   cause = (const int*)  d_in[2];
    const float* W1    = (const float*)d_in[3];
    const float* b1    = (const float*)d_in[4];
    const float* W2    = (const float*)d_in[5];
    const float* b2    = (const float*)d_in[6];
    const float* W3    = (const float*)d_in[7];
    const float* b3    = (const float*)d_in[8];
    float* out = (float*)d_out;

    dim3 grid(OO / OTILE, BB / 256);   // (64, 32) = 2048 blocks
    medil_kernel<<<grid, 128, SMEM_BYTES>>>(x, noise, cause, W1, b1, W2, b2, W3, b3, out);
}